// round 15
// baseline (speedup 1.0000x reference)
#include <cuda_runtime.h>
#include <math.h>
#include <float.h>

#define N_      4
#define C_      21
#define H_      512
#define W_      512
#define HW      (H_*W_)
#define PH      171
#define PP      (PH*PH)      // 29241
#define NH      169
#define M_      (NH*NH)      // 28561
#define NC      (N_*C_)      // 84
#define ALPHA   5e-4
#define CLIPMIN 1e-6f
#define RSPLIT  7
#define ROWCH   ((NH + RSPLIT - 1) / RSPLIT)   // 25
#define GRAMSZ  (NC*3*81)
#define CSPLIT  3
#define CPB     (C_ / CSPLIT)    // 7 classes per block
#define FULLM   0xffffffffu

// ------------------------- device scratch ----------------------------------
// +PH padding: gram kernels prefetch one row beyond the last window row.
__device__ float    g_la[NC*PP + PH];
__device__ float    g_pr[NC*PP + PH];
__device__ unsigned g_labbits[NC*PH*6 + 8];   // per (nc,row): 6 x 32-col bitmask
__device__ double   g_gram[GRAMSZ];
__device__ double   g_bce;      // zero-init at load; self-reset each run
__device__ double   g_valid;
__device__ double   g_rmi;
__device__ int      g_done;

// ------------------------- kernel 1: pool + BCE ----------------------------
// Block = (pooled row i, batch n, class-group zc). Handles CPB classes.
// Label slot-masks live in smem (not registers) so the class loop runs at
// low register pressure -> 6+ CTAs/SM.
__global__ void __launch_bounds__(192, 6)
k_pool_bce(const float* __restrict__ logits, const void* __restrict__ labv) {
    const int i   = blockIdx.x;        // pooled row 0..170
    const int n   = blockIdx.y;
    const int zc  = blockIdx.z;
    const int c0  = zc * CPB;
    const int tid = threadIdx.x;
    const int y0  = 3*i - 1;
    const bool rowsok = (i > 0);       // i==0 is the only row-clipped block

    // zero gram accumulators (zc==0 blocks; complete before gram launch)
    if (zc == 0) {
        const int gt = (n*gridDim.x + i)*192 + tid;
        if (gt < GRAMSZ) g_gram[gt] = 0.0;
    }

    __shared__ int      s_is64;
    __shared__ float4   slog4[2][3][128];
    __shared__ int      slab[3][512];
    __shared__ unsigned m9[CPB][192];   // per-class 9-bit label slot-masks

    // parallel dtype sniff: int64 labels (<21) have zero odd int32 words
    if (tid < 32) {
        const int* p = (const int*)labv;
        const int o = p[2*tid + 1] | p[2*(tid + 32) + 1];
        const unsigned bal = __ballot_sync(FULLM, o != 0);
        if (tid == 0) s_is64 = (bal == 0);
    }
    __syncthreads();

    // stage labels for the 3 rows (validated class or -1)
    {
        const bool is64 = (s_is64 != 0);
        const long long* L64 = (const long long*)labv;
        const int*       L32 = (const int*)labv;
        #pragma unroll
        for (int k = tid; k < 3*512; k += 192) {
            const int r = k >> 9, x = k & 511;
            const int y = y0 + r;
            int lv = -1;
            if ((unsigned)y < (unsigned)H_) {
                const int gidx = (n*H_ + y)*W_ + x;
                lv = is64 ? (int)L64[gidx] : L32[gidx];
            }
            slab[r][x] = ((unsigned)lv < (unsigned)C_) ? lv : -1;
        }
    }

    const int ncbase = n * C_;
    const float* __restrict__ lbase = logits + (size_t)ncbase * HW;

    auto stage = [&](int b, int c) {
        const float* __restrict__ src = lbase + (size_t)c * HW + y0*W_;
        if (rowsok) {
            #pragma unroll
            for (int k = tid; k < 3*128; k += 192) {
                const int r = k >> 7, q = k & 127;
                slog4[b][r][q] = *(const float4*)(src + r*W_ + 4*q);
            }
        } else {
            #pragma unroll
            for (int k = tid; k < 3*128; k += 192) {
                const int r = k >> 7, q = k & 127;
                float4 v = make_float4(0.f, 0.f, 0.f, 0.f);
                if (r > 0) v = *(const float4*)(src + r*W_ + 4*q);
                slog4[b][r][q] = v;
            }
        }
    };

    stage(0, c0);
    __syncthreads();   // labels + first class rows ready

    // per-cell label metadata; labk lives only in this scope (regs freed
    // before the class loop; per-class masks go to smem)
    const int j  = tid;                // cell column
    const int x0 = 3*j - 1;
    int xs[3];                         // clamped column offsets (3 regs)
    unsigned vmask = 0, labmask = 0;
    int valid = 0;
    {
        int labk[9];
        if (j < PH) {
            #pragma unroll
            for (int dx = 0; dx < 3; dx++) {
                const int x = x0 + dx;
                xs[dx] = (x < 0) ? 0 : ((x > 511) ? 511 : x);
            }
            #pragma unroll
            for (int s = 0; s < 9; s++) {
                const int x = x0 + (s % 3);
                const bool inb = ((unsigned)x < (unsigned)W_);
                const int lv = inb ? slab[s/3][x] : -1;
                labk[s] = lv;
                if (lv >= 0) { vmask |= (1u << s); valid++; labmask |= (1u << lv); }
            }
        } else {
            #pragma unroll
            for (int s = 0; s < 9; s++) labk[s] = -1;
            xs[0] = xs[1] = xs[2] = 0;
        }
        // per-class slot masks into smem
        #pragma unroll
        for (int cc = 0; cc < CPB; cc++) {
            unsigned m = 0;
            #pragma unroll
            for (int s = 0; s < 9; s++)
                m |= (labk[s] == c0 + cc) ? (1u << s) : 0u;
            m9[cc][tid] = m;
        }
    }

    // label bitmasks (zc==0 only): warp w covers columns w*32..w*32+31
    if (zc == 0) {
        const int lane = tid & 31, wid = tid >> 5;
        #pragma unroll
        for (int c = 0; c < C_; c++) {
            const unsigned bits = __ballot_sync(FULLM, (labmask >> c) & 1u);
            if (lane == 0)
                g_labbits[(size_t)((ncbase + c)*PH + i)*6 + wid] = bits;
        }
    }

    float bce_acc = 0.f;
    const int cell = i*PH + j;
    const bool full = (vmask == 0x1FFu);
    float* __restrict__ pp = g_pr + (size_t)(ncbase + c0)*PP + cell;
    float* __restrict__ pl = g_la + (size_t)(ncbase + c0)*PP + cell;

    #pragma unroll 1
    for (int cc = 0; cc < CPB; cc++) {
        const int c = c0 + cc;
        const int b = cc & 1;
        if (cc + 1 < CPB) stage(1 - b, c + 1);   // prefetch next class

        if (j < PH) {
            const float* slog = (const float*)slog4[b];   // [3][512]
            const unsigned lm = m9[cc][tid];
            float maxv = -FLT_MAX;
            float prod = 1.f;          // prod over valid pixels of (1+e^{-|x|})
            float racc = 0.f;          // sum relu(lab==c ? -x : x)
            if (full) {
                #pragma unroll
                for (int s = 0; s < 9; s++) {
                    const float xv = slog[xs[s % 3] + (s/3)*512];
                    maxv = fmaxf(maxv, xv);
                    const float t = __expf(-fabsf(xv));
                    prod = fmaf(prod, t, prod);
                    const float xv2 = ((lm >> s) & 1u) ? -xv : xv;
                    racc += fmaxf(xv2, 0.f);
                }
            } else {
                #pragma unroll
                for (int s = 0; s < 9; s++) {
                    float xv = slog[xs[s % 3] + (s/3)*512];
                    xv = ((vmask >> s) & 1u) ? xv : -FLT_MAX;
                    maxv = fmaxf(maxv, xv);
                    const float t = __expf(-fabsf(xv));
                    prod = fmaf(prod, t, prod);
                    const float xv2 = ((lm >> s) & 1u) ? -xv : xv;
                    racc += fmaxf(xv2, 0.f);
                }
            }
            bce_acc += racc + __logf(prod);
            // sigmoid(maxv); empty cell: maxv=-FLT_MAX -> exp=inf -> sg=0
            const float sg = __fdividef(1.f, 1.f + __expf(-maxv));
            pp[0] = sg + CLIPMIN;
            pl[0] = ((labmask >> c) & 1u) ? 1.f : 0.f;
        }
        pp += PP;
        pl += PP;
        __syncthreads();   // next buffer staged AND this buffer's compute done
    }

    // block reduce -> atomic (valid only from zc==0 to avoid triple count)
    double b = (double)bce_acc, v = (zc == 0) ? (double)valid : 0.0;
    #pragma unroll
    for (int o = 16; o > 0; o >>= 1) {
        b += __shfl_down_sync(FULLM, b, o);
        v += __shfl_down_sync(FULLM, v, o);
    }
    __shared__ double sb[6], sv[6];
    const int lane = tid & 31, wid = tid >> 5;
    if (lane == 0) { sb[wid] = b; sv[wid] = v; }
    __syncthreads();
    if (tid == 0) {
        double tb = 0, tv = 0;
        #pragma unroll
        for (int w = 0; w < 6; w++) { tb += sb[w]; tv += sv[w]; }
        atomicAdd(&g_bce, tb);
        if (zc == 0) atomicAdd(&g_valid, tv);
    }
}

// ------------------------- gram epilogue: block reduce, few atomics --------
template<int NACC>
__device__ __forceinline__ void block_reduce(const float* acc,
                                             float (*sred)[54],
                                             float* outv /*size NACC*/) {
    const int lane = threadIdx.x & 31, wid = threadIdx.x >> 5;
    #pragma unroll
    for (int k = 0; k < NACC; k++) {
        float x = acc[k];
        #pragma unroll
        for (int o = 16; o > 0; o >>= 1) x += __shfl_xor_sync(FULLM, x, o);
        if (lane == 0) sred[wid][k] = x;
    }
    __syncthreads();
    if (threadIdx.x < NACC) {
        float s = 0.f;
        #pragma unroll
        for (int w = 0; w < 6; w++) s += sred[w][threadIdx.x];
        outv[threadIdx.x] = s;
    }
}

// ------------------------- la-self Gram via popcount -----------------------
__device__ __forceinline__ void self_la_bits(const unsigned* __restrict__ Wb,
                                             int i0, int i1,
                                             double* __restrict__ out,
                                             float (*sred)[54]) {
    int acc[54];
    #pragma unroll
    for (int k = 0; k < 54; k++) acc[k] = 0;

    const int t = threadIdx.x;
    const int nrows = i1 - i0;
    if (t < 6*nrows) {
        const int q = t % 6;
        const int i = i0 + t / 6;
        const unsigned vm = (q == 5) ? 0x1FFu : 0xFFFFFFFFu;  // samples j<169
        unsigned bd[9];
        #pragma unroll
        for (int dy = 0; dy < 3; dy++) {
            const unsigned lo = Wb[(size_t)(i+dy)*6 + q];
            const unsigned hi = (q < 5) ? Wb[(size_t)(i+dy)*6 + q + 1] : 0u;
            #pragma unroll
            for (int dx = 0; dx < 3; dx++)
                bd[dy*3+dx] = __funnelshift_r(lo, hi, dx) & vm;
        }
        int k = 0;
        #pragma unroll
        for (int d = 0; d < 9; d++)
            #pragma unroll
            for (int e = d; e < 9; e++)
                acc[k++] += __popc(bd[d] & bd[e]);
        #pragma unroll
        for (int d = 0; d < 9; d++) acc[45 + d] += __popc(bd[d]);
    }

    float facc[54];
    #pragma unroll
    for (int k = 0; k < 54; k++) facc[k] = (float)acc[k];
    __shared__ float outv[54];
    block_reduce<54>(facc, sred, outv);
    if (threadIdx.x < 54) atomicAdd(&out[threadIdx.x], (double)outv[threadIdx.x]);
}

// ------------------------- float gram bodies -------------------------------
__device__ __forceinline__ void self_body(const float* __restrict__ A0,
                                          int i0, int i1,
                                          double* __restrict__ out, int j,
                                          float (*sred)[54]) {
    float acc[54];
    #pragma unroll
    for (int k = 0; k < 54; k++) acc[k] = 0.f;

    if (j < NH) {
        const float* __restrict__ A = A0 + i0*PH + j;
        float w0[3], w1[3], nxt[3];
        #pragma unroll
        for (int c = 0; c < 3; c++) w0[c] = A[c];
        A += PH;
        #pragma unroll
        for (int c = 0; c < 3; c++) w1[c] = A[c];
        A += PH;
        #pragma unroll
        for (int c = 0; c < 3; c++) nxt[c] = A[c];
        A += PH;

        #pragma unroll 2
        for (int i = i0; i < i1; i++) {
            float a[9] = { w0[0], w0[1], w0[2],
                           w1[0], w1[1], w1[2],
                           nxt[0], nxt[1], nxt[2] };
            #pragma unroll
            for (int c = 0; c < 3; c++) nxt[c] = A[c];
            A += PH;

            int k = 0;
            #pragma unroll
            for (int d = 0; d < 9; d++)
                #pragma unroll
                for (int e = d; e < 9; e++)
                    acc[k++] += a[d] * a[e];
            #pragma unroll
            for (int d = 0; d < 9; d++) acc[45 + d] += a[d];

            #pragma unroll
            for (int c = 0; c < 3; c++) { w0[c] = w1[c]; w1[c] = a[6 + c]; }
        }
    }

    __shared__ float outv[54];
    block_reduce<54>(acc, sred, outv);
    if (threadIdx.x < 54) atomicAdd(&out[threadIdx.x], (double)outv[threadIdx.x]);
}

template<int EL, int NE>
__device__ __forceinline__ void cross_body(const float* __restrict__ Ab,
                                           const float* __restrict__ Bb,
                                           int i0, int i1,
                                           double* __restrict__ out, int j,
                                           float (*sred)[54]) {
    float acc[9*NE];
    #pragma unroll
    for (int k = 0; k < 9*NE; k++) acc[k] = 0.f;

    if (j < NH) {
        const float* __restrict__ A = Ab + i0*PH + j;
        const float* __restrict__ B = Bb + i0*PH + j;
        float wa0[3], wa1[3], na[3];
        float wb0[3], wb1[3], nb[3];
        #pragma unroll
        for (int c = 0; c < 3; c++) { wa0[c] = A[c]; wb0[c] = B[c]; }
        A += PH; B += PH;
        #pragma unroll
        for (int c = 0; c < 3; c++) { wa1[c] = A[c]; wb1[c] = B[c]; }
        A += PH; B += PH;
        #pragma unroll
        for (int c = 0; c < 3; c++) { na[c] = A[c]; nb[c] = B[c]; }
        A += PH; B += PH;

        #pragma unroll 2
        for (int i = i0; i < i1; i++) {
            float a[9] = { wa0[0], wa0[1], wa0[2],
                           wa1[0], wa1[1], wa1[2],
                           na[0],  na[1],  na[2] };
            float b[9] = { wb0[0], wb0[1], wb0[2],
                           wb1[0], wb1[1], wb1[2],
                           nb[0],  nb[1],  nb[2] };
            #pragma unroll
            for (int c = 0; c < 3; c++) { na[c] = A[c]; nb[c] = B[c]; }
            A += PH; B += PH;

            #pragma unroll
            for (int d = 0; d < 9; d++)
                #pragma unroll
                for (int e = 0; e < NE; e++)
                    acc[d*NE + e] += a[d] * b[EL + e];

            #pragma unroll
            for (int c = 0; c < 3; c++) {
                wa0[c] = wa1[c]; wa1[c] = a[6 + c];
                wb0[c] = wb1[c]; wb1[c] = b[6 + c];
            }
        }
    }

    __shared__ float outv[54];
    block_reduce<9*NE>(acc, sred, outv);
    if (threadIdx.x < 9*NE) {
        const int d = threadIdx.x / NE, e = EL + (threadIdx.x % NE);
        atomicAdd(&out[d*9 + e], (double)outv[threadIdx.x]);
    }
}

// ------------------------- kernel 2: all Grams, one launch -----------------
__global__ void __launch_bounds__(192)
k_gram_all() {
    __shared__ float sred[6][54];
    const int nc = blockIdx.x;
    const int z  = blockIdx.z;
    const int j  = threadIdx.x;
    const int i0 = blockIdx.y * ROWCH;
    const int i1 = (i0 + ROWCH < NH) ? (i0 + ROWCH) : NH;
    const size_t base = (size_t)nc * PP;
    double* __restrict__ out = g_gram + (size_t)(nc*3) * 81;

    if (z == 0)      self_la_bits(g_labbits + (size_t)nc*PH*6, i0, i1, out, sred);
    else if (z == 1) self_body(g_pr + base, i0, i1, out + 81, j, sred);
    else if (z == 2) cross_body<0,5>(g_la + base, g_pr + base, i0, i1, out + 162, j, sred);
    else             cross_body<5,4>(g_la + base, g_pr + base, i0, i1, out + 162, j, sred);
}

// ------------------------- kernel 3: linear algebra + last-block combine ---
__global__ void __launch_bounds__(32)
k_finalize(float* __restrict__ outp) {
    const int nc = blockIdx.x;
    const int d  = threadIdx.x;
    const int dd = (d < 9) ? d : 0;

    const double* __restrict__ G0 = g_gram + (size_t)(nc*3 + 0)*81;
    const double* __restrict__ G1 = g_gram + (size_t)(nc*3 + 1)*81;
    const double* __restrict__ G2 = g_gram + (size_t)(nc*3 + 2)*81;

    const double invM = 1.0 / (double)M_;
    const double sla_d = G0[45 + dd], spr_d = G1[45 + dd];

    float Cr[9], Pr[9], Br[9];
    #pragma unroll
    for (int e = 0; e < 9; e++) {
        const int lo = (dd < e) ? dd : e;
        const int hi = (dd < e) ? e : dd;
        const int tri = lo*9 - (lo*(lo-1))/2 + (hi - lo);
        const double sla_e = G0[45 + e], spr_e = G1[45 + e];
        Cr[e] = (float)(G0[tri] - sla_d*sla_e*invM + ((e == dd) ? ALPHA : 0.0));
        Pr[e] = (float)(G1[tri] - spr_d*spr_e*invM + ((e == dd) ? ALPHA : 0.0));
        Br[e] = (float)(G2[dd*9 + e] - sla_d*spr_e*invM);
    }

    float Lr[9], Dinv[9];
    #pragma unroll
    for (int k = 0; k < 9; k++) {
        const float pkk = __shfl_sync(FULLM, Pr[k], k);
        const float rs  = rsqrtf(fmaxf(pkk, 1e-30f));
        const float ldk = Pr[k] * rs;
        Lr[k]   = ldk;
        Dinv[k] = rs;
        #pragma unroll
        for (int j = 0; j < 9; j++)
            if (j > k) Pr[j] -= ldk * __shfl_sync(FULLM, ldk, j);
    }

    float Wr[9];
    #pragma unroll
    for (int e = 0; e < 9; e++) {
        float s = Br[e];
        #pragma unroll
        for (int k = 0; k < 9; k++)
            if (k < e) s -= Wr[k] * __shfl_sync(FULLM, Lr[k], e);
        Wr[e] = s * Dinv[e];
    }

    #pragma unroll
    for (int e = 0; e < 9; e++) {
        float s = 0.f;
        #pragma unroll
        for (int k = 0; k < 9; k++)
            s += Wr[k] * __shfl_sync(FULLM, Wr[k], e);
        Cr[e] -= s;
    }

    float dprod = 1.f;
    #pragma unroll
    for (int k = 0; k < 9; k++) {
        const float akk = __shfl_sync(FULLM, Cr[k], k);
        const float as  = fmaxf(akk, 1e-30f);
        const float rs  = rsqrtf(as);
        const float lkk = as * rs;
        dprod *= (lkk + 1e-8f);
        const float ldk = Cr[k] * rs;
        #pragma unroll
        for (int j = 0; j < 9; j++)
            if (j > k) Cr[j] -= ldk * __shfl_sync(FULLM, ldk, j);
    }

    // last block through combines, writes output, and self-resets state
    if (d == 0) {
        atomicAdd(&g_rmi, (double)logf(dprod));
        __threadfence();
        const int prev = atomicAdd(&g_done, 1);
        if (prev == NC - 1) {
            const double rmi_total = g_rmi / (double)(N_ * 9);
            const double bce_loss  = g_bce / (g_valid + 1.0);
            outp[0] = (float)(0.5 * bce_loss + 0.5 * rmi_total);
            // reset for next graph replay (all NC blocks already arrived)
            g_bce = 0.0; g_valid = 0.0; g_rmi = 0.0;
            __threadfence();
            g_done = 0;
        }
    }
}

// ------------------------- launch ------------------------------------------
extern "C" void kernel_launch(void* const* d_in, const int* in_sizes, int n_in,
                              void* d_out, int out_size) {
    const float* logits = (const float*)d_in[0];
    const void*  labels = d_in[1];

    dim3 gp(PH, N_, CSPLIT);
    k_pool_bce<<<gp, 192>>>(logits, labels);
    dim3 g2(NC, RSPLIT, 4);
    k_gram_all<<<g2, 192>>>();
    k_finalize<<<NC, 32>>>((float*)d_out);
}

// round 16
// speedup vs baseline: 1.0762x; 1.0762x over previous
#include <cuda_runtime.h>
#include <math.h>
#include <float.h>

#define N_      4
#define C_      21
#define H_      512
#define W_      512
#define HW      (H_*W_)
#define PH      171
#define PP      (PH*PH)      // 29241
#define NH      169
#define M_      (NH*NH)      // 28561
#define NC      (N_*C_)      // 84
#define ALPHA   5e-4
#define CLIPMIN 1e-6f
#define RSPLIT  7
#define ROWCH   ((NH + RSPLIT - 1) / RSPLIT)   // 25
#define GRAMSZ  (NC*3*81)
#define CSPLIT  3
#define CPB     (C_ / CSPLIT)    // 7 classes per block
#define FULLM   0xffffffffu

// ------------------------- device scratch ----------------------------------
// +PH padding: gram kernels prefetch one row beyond the last window row.
__device__ float    g_la[NC*PP + PH];
__device__ float    g_pr[NC*PP + PH];
__device__ unsigned g_labbits[NC*PH*6 + 8];   // per (nc,row): 6 x 32-col bitmask
__device__ double   g_gram[GRAMSZ];
__device__ double   g_bce;      // zero-init at load; self-reset each run
__device__ double   g_valid;
__device__ double   g_rmi;
__device__ int      g_done;

// ------------------------- cp.async helpers --------------------------------
__device__ __forceinline__ void cp_async16(unsigned saddr, const void* gaddr,
                                           int szbytes) {
    asm volatile("cp.async.cg.shared.global [%0], [%1], 16, %2;\n"
                 :: "r"(saddr), "l"(gaddr), "r"(szbytes) : "memory");
}
#define CP_COMMIT() asm volatile("cp.async.commit_group;\n" ::: "memory")
#define CP_WAIT0()  asm volatile("cp.async.wait_group 0;\n" ::: "memory")

// ------------------------- kernel 1: pool + BCE ----------------------------
// Block = (pooled row i, batch n, class-group zc). Handles CPB classes.
// Staging via cp.async double-buffer: wait_group(0) -> barrier -> issue next
// class's copy -> compute current. The barrier never drains the prefetch.
__global__ void __launch_bounds__(192)
k_pool_bce(const float* __restrict__ logits, const void* __restrict__ labv) {
    const int i   = blockIdx.x;        // pooled row 0..170
    const int n   = blockIdx.y;
    const int zc  = blockIdx.z;
    const int c0  = zc * CPB;
    const int tid = threadIdx.x;
    const int y0  = 3*i - 1;

    // zero gram accumulators (zc==0 blocks; complete before gram launch)
    if (zc == 0) {
        const int gt = (n*gridDim.x + i)*192 + tid;
        if (gt < GRAMSZ) g_gram[gt] = 0.0;
    }

    __shared__ int    s_is64;
    __shared__ float4 slog4[2][3][128];
    __shared__ int    slab[3][512];

    const int ncbase = n * C_;
    const float* __restrict__ lbase = logits + (size_t)ncbase * HW;

    // per-thread staging slots: k0=tid (row r0 in {0,1}), k1=tid+192 (r in {1,2})
    const int r0 = tid >> 7, q0 = tid & 127;
    const int k1 = tid + 192;
    const int r1 = k1 >> 7,  q1 = k1 & 127;
    const int sz0 = (i > 0 || r0 > 0) ? 16 : 0;      // only i==0,r==0 clipped
    const int goff0 = ((y0 + r0 < 0) ? 0 : (y0 + r0))*W_ + 4*q0;
    const int goff1 = (y0 + r1)*W_ + 4*q1;
    const unsigned sbase0 = (unsigned)__cvta_generic_to_shared(&slog4[0][0][0]);
    const unsigned dst0a = sbase0 + tid*16, dst1a = sbase0 + k1*16;
    const unsigned dst0b = dst0a + 3*128*16, dst1b = dst1a + 3*128*16;

    auto stage = [&](int b, int c) {
        const float* __restrict__ src = lbase + (size_t)c * HW;
        cp_async16(b ? dst0b : dst0a, src + goff0, sz0);
        cp_async16(b ? dst1b : dst1a, src + goff1, 16);
        CP_COMMIT();
    };

    // kick off first class copy ASAP (independent of label staging)
    stage(0, c0);

    // parallel dtype sniff: int64 labels (<21) have zero odd int32 words
    if (tid < 32) {
        const int* p = (const int*)labv;
        const int o = p[2*tid + 1] | p[2*(tid + 32) + 1];
        const unsigned bal = __ballot_sync(FULLM, o != 0);
        if (tid == 0) s_is64 = (bal == 0);
    }
    __syncthreads();

    // stage labels for the 3 rows (validated class or -1)
    {
        const bool is64 = (s_is64 != 0);
        const long long* L64 = (const long long*)labv;
        const int*       L32 = (const int*)labv;
        #pragma unroll
        for (int k = tid; k < 3*512; k += 192) {
            const int r = k >> 9, x = k & 511;
            const int y = y0 + r;
            int lv = -1;
            if ((unsigned)y < (unsigned)H_) {
                const int gidx = (n*H_ + y)*W_ + x;
                lv = is64 ? (int)L64[gidx] : L32[gidx];
            }
            slab[r][x] = ((unsigned)lv < (unsigned)C_) ? lv : -1;
        }
    }
    __syncthreads();

    // per-cell label metadata (registers, compile-time indexed)
    const int j  = tid;                // cell column
    const int x0 = 3*j - 1;
    int labk[9];
    int xs[3];                         // clamped column offsets
    unsigned vmask = 0, labmask = 0;
    int valid = 0;
    if (j < PH) {
        #pragma unroll
        for (int dx = 0; dx < 3; dx++) {
            const int x = x0 + dx;
            xs[dx] = (x < 0) ? 0 : ((x > 511) ? 511 : x);
        }
        #pragma unroll
        for (int s = 0; s < 9; s++) {
            const int x = x0 + (s % 3);
            const bool inb = ((unsigned)x < (unsigned)W_);
            const int lv = inb ? slab[s/3][x] : -1;
            labk[s] = lv;
            if (lv >= 0) { vmask |= (1u << s); valid++; labmask |= (1u << lv); }
        }
    }

    // label bitmasks (zc==0 only): warp w covers columns w*32..w*32+31
    if (zc == 0) {
        const int lane = tid & 31, wid = tid >> 5;
        #pragma unroll
        for (int c = 0; c < C_; c++) {
            const unsigned bits = __ballot_sync(FULLM, (labmask >> c) & 1u);
            if (lane == 0)
                g_labbits[(size_t)((ncbase + c)*PH + i)*6 + wid] = bits;
        }
    }

    float bce_acc = 0.f;
    const int cell = i*PH + j;
    const bool full = (vmask == 0x1FFu);
    float* __restrict__ pp = g_pr + (size_t)(ncbase + c0)*PP + cell;
    float* __restrict__ pl = g_la + (size_t)(ncbase + c0)*PP + cell;

    #pragma unroll 1
    for (int cc = 0; cc < CPB; cc++) {
        const int c = c0 + cc;
        const int b = cc & 1;
        CP_WAIT0();          // class-c copy complete (issued last iteration)
        __syncthreads();     // all threads: data visible, prev compute done
        if (cc + 1 < CPB) stage(1 - b, c + 1);   // overlaps compute below

        if (j < PH) {
            const float* slog = (const float*)slog4[b];   // [3][512]
            float maxv = -FLT_MAX;
            float prod = 1.f;          // prod over valid pixels of (1+e^{-|x|})
            float racc = 0.f;          // sum relu(lab==c ? -x : x)
            if (full) {
                #pragma unroll
                for (int s = 0; s < 9; s++) {
                    const float xv = slog[xs[s % 3] + (s/3)*512];
                    maxv = fmaxf(maxv, xv);
                    const float t = __expf(-fabsf(xv));
                    prod = fmaf(prod, t, prod);
                    const float xv2 = (labk[s] == c) ? -xv : xv;
                    racc += fmaxf(xv2, 0.f);
                }
            } else {
                #pragma unroll
                for (int s = 0; s < 9; s++) {
                    float xv = slog[xs[s % 3] + (s/3)*512];
                    xv = ((vmask >> s) & 1u) ? xv : -FLT_MAX;
                    maxv = fmaxf(maxv, xv);
                    const float t = __expf(-fabsf(xv));
                    prod = fmaf(prod, t, prod);
                    const float xv2 = (labk[s] == c) ? -xv : xv;
                    racc += fmaxf(xv2, 0.f);
                }
            }
            bce_acc += racc + __logf(prod);
            // sigmoid(maxv); empty cell: maxv=-FLT_MAX -> exp=inf -> sg=0
            const float sg = __fdividef(1.f, 1.f + __expf(-maxv));
            pp[0] = sg + CLIPMIN;
            pl[0] = ((labmask >> c) & 1u) ? 1.f : 0.f;
        }
        pp += PP;
        pl += PP;
    }

    // block reduce -> atomic (valid only from zc==0 to avoid triple count)
    double b = (double)bce_acc, v = (zc == 0) ? (double)valid : 0.0;
    #pragma unroll
    for (int o = 16; o > 0; o >>= 1) {
        b += __shfl_down_sync(FULLM, b, o);
        v += __shfl_down_sync(FULLM, v, o);
    }
    __shared__ double sb[6], sv[6];
    const int lane = tid & 31, wid = tid >> 5;
    if (lane == 0) { sb[wid] = b; sv[wid] = v; }
    __syncthreads();
    if (tid == 0) {
        double tb = 0, tv = 0;
        #pragma unroll
        for (int w = 0; w < 6; w++) { tb += sb[w]; tv += sv[w]; }
        atomicAdd(&g_bce, tb);
        if (zc == 0) atomicAdd(&g_valid, tv);
    }
}

// ------------------------- gram epilogue: block reduce, few atomics --------
template<int NACC>
__device__ __forceinline__ void block_reduce(const float* acc,
                                             float (*sred)[54],
                                             float* outv /*size NACC*/) {
    const int lane = threadIdx.x & 31, wid = threadIdx.x >> 5;
    #pragma unroll
    for (int k = 0; k < NACC; k++) {
        float x = acc[k];
        #pragma unroll
        for (int o = 16; o > 0; o >>= 1) x += __shfl_xor_sync(FULLM, x, o);
        if (lane == 0) sred[wid][k] = x;
    }
    __syncthreads();
    if (threadIdx.x < NACC) {
        float s = 0.f;
        #pragma unroll
        for (int w = 0; w < 6; w++) s += sred[w][threadIdx.x];
        outv[threadIdx.x] = s;
    }
}

// ------------------------- la-self Gram via popcount -----------------------
__device__ __forceinline__ void self_la_bits(const unsigned* __restrict__ Wb,
                                             int i0, int i1,
                                             double* __restrict__ out,
                                             float (*sred)[54]) {
    int acc[54];
    #pragma unroll
    for (int k = 0; k < 54; k++) acc[k] = 0;

    const int t = threadIdx.x;
    const int nrows = i1 - i0;
    if (t < 6*nrows) {
        const int q = t % 6;
        const int i = i0 + t / 6;
        const unsigned vm = (q == 5) ? 0x1FFu : 0xFFFFFFFFu;  // samples j<169
        unsigned bd[9];
        #pragma unroll
        for (int dy = 0; dy < 3; dy++) {
            const unsigned lo = Wb[(size_t)(i+dy)*6 + q];
            const unsigned hi = (q < 5) ? Wb[(size_t)(i+dy)*6 + q + 1] : 0u;
            #pragma unroll
            for (int dx = 0; dx < 3; dx++)
                bd[dy*3+dx] = __funnelshift_r(lo, hi, dx) & vm;
        }
        int k = 0;
        #pragma unroll
        for (int d = 0; d < 9; d++)
            #pragma unroll
            for (int e = d; e < 9; e++)
                acc[k++] += __popc(bd[d] & bd[e]);
        #pragma unroll
        for (int d = 0; d < 9; d++) acc[45 + d] += __popc(bd[d]);
    }

    float facc[54];
    #pragma unroll
    for (int k = 0; k < 54; k++) facc[k] = (float)acc[k];
    __shared__ float outv[54];
    block_reduce<54>(facc, sred, outv);
    if (threadIdx.x < 54) atomicAdd(&out[threadIdx.x], (double)outv[threadIdx.x]);
}

// ------------------------- float gram bodies -------------------------------
__device__ __forceinline__ void self_body(const float* __restrict__ A0,
                                          int i0, int i1,
                                          double* __restrict__ out, int j,
                                          float (*sred)[54]) {
    float acc[54];
    #pragma unroll
    for (int k = 0; k < 54; k++) acc[k] = 0.f;

    if (j < NH) {
        const float* __restrict__ A = A0 + i0*PH + j;
        float w0[3], w1[3], nxt[3];
        #pragma unroll
        for (int c = 0; c < 3; c++) w0[c] = A[c];
        A += PH;
        #pragma unroll
        for (int c = 0; c < 3; c++) w1[c] = A[c];
        A += PH;
        #pragma unroll
        for (int c = 0; c < 3; c++) nxt[c] = A[c];
        A += PH;

        #pragma unroll 2
        for (int i = i0; i < i1; i++) {
            float a[9] = { w0[0], w0[1], w0[2],
                           w1[0], w1[1], w1[2],
                           nxt[0], nxt[1], nxt[2] };
            #pragma unroll
            for (int c = 0; c < 3; c++) nxt[c] = A[c];
            A += PH;

            int k = 0;
            #pragma unroll
            for (int d = 0; d < 9; d++)
                #pragma unroll
                for (int e = d; e < 9; e++)
                    acc[k++] += a[d] * a[e];
            #pragma unroll
            for (int d = 0; d < 9; d++) acc[45 + d] += a[d];

            #pragma unroll
            for (int c = 0; c < 3; c++) { w0[c] = w1[c]; w1[c] = a[6 + c]; }
        }
    }

    __shared__ float outv[54];
    block_reduce<54>(acc, sred, outv);
    if (threadIdx.x < 54) atomicAdd(&out[threadIdx.x], (double)outv[threadIdx.x]);
}

template<int EL, int NE>
__device__ __forceinline__ void cross_body(const float* __restrict__ Ab,
                                           const float* __restrict__ Bb,
                                           int i0, int i1,
                                           double* __restrict__ out, int j,
                                           float (*sred)[54]) {
    float acc[9*NE];
    #pragma unroll
    for (int k = 0; k < 9*NE; k++) acc[k] = 0.f;

    if (j < NH) {
        const float* __restrict__ A = Ab + i0*PH + j;
        const float* __restrict__ B = Bb + i0*PH + j;
        float wa0[3], wa1[3], na[3];
        float wb0[3], wb1[3], nb[3];
        #pragma unroll
        for (int c = 0; c < 3; c++) { wa0[c] = A[c]; wb0[c] = B[c]; }
        A += PH; B += PH;
        #pragma unroll
        for (int c = 0; c < 3; c++) { wa1[c] = A[c]; wb1[c] = B[c]; }
        A += PH; B += PH;
        #pragma unroll
        for (int c = 0; c < 3; c++) { na[c] = A[c]; nb[c] = B[c]; }
        A += PH; B += PH;

        #pragma unroll 2
        for (int i = i0; i < i1; i++) {
            float a[9] = { wa0[0], wa0[1], wa0[2],
                           wa1[0], wa1[1], wa1[2],
                           na[0],  na[1],  na[2] };
            float b[9] = { wb0[0], wb0[1], wb0[2],
                           wb1[0], wb1[1], wb1[2],
                           nb[0],  nb[1],  nb[2] };
            #pragma unroll
            for (int c = 0; c < 3; c++) { na[c] = A[c]; nb[c] = B[c]; }
            A += PH; B += PH;

            #pragma unroll
            for (int d = 0; d < 9; d++)
                #pragma unroll
                for (int e = 0; e < NE; e++)
                    acc[d*NE + e] += a[d] * b[EL + e];

            #pragma unroll
            for (int c = 0; c < 3; c++) {
                wa0[c] = wa1[c]; wa1[c] = a[6 + c];
                wb0[c] = wb1[c]; wb1[c] = b[6 + c];
            }
        }
    }

    __shared__ float outv[54];
    block_reduce<9*NE>(acc, sred, outv);
    if (threadIdx.x < 9*NE) {
        const int d = threadIdx.x / NE, e = EL + (threadIdx.x % NE);
        atomicAdd(&out[d*9 + e], (double)outv[threadIdx.x]);
    }
}

// ------------------------- kernel 2: all Grams, one launch -----------------
__global__ void __launch_bounds__(192)
k_gram_all() {
    __shared__ float sred[6][54];
    const int nc = blockIdx.x;
    const int z  = blockIdx.z;
    const int j  = threadIdx.x;
    const int i0 = blockIdx.y * ROWCH;
    const int i1 = (i0 + ROWCH < NH) ? (i0 + ROWCH) : NH;
    const size_t base = (size_t)nc * PP;
    double* __restrict__ out = g_gram + (size_t)(nc*3) * 81;

    if (z == 0)      self_la_bits(g_labbits + (size_t)nc*PH*6, i0, i1, out, sred);
    else if (z == 1) self_body(g_pr + base, i0, i1, out + 81, j, sred);
    else if (z == 2) cross_body<0,5>(g_la + base, g_pr + base, i0, i1, out + 162, j, sred);
    else             cross_body<5,4>(g_la + base, g_pr + base, i0, i1, out + 162, j, sred);
}

// ------------------------- kernel 3: linear algebra + last-block combine ---
__global__ void __launch_bounds__(32)
k_finalize(float* __restrict__ outp) {
    const int nc = blockIdx.x;
    const int d  = threadIdx.x;
    const int dd = (d < 9) ? d : 0;

    const double* __restrict__ G0 = g_gram + (size_t)(nc*3 + 0)*81;
    const double* __restrict__ G1 = g_gram + (size_t)(nc*3 + 1)*81;
    const double* __restrict__ G2 = g_gram + (size_t)(nc*3 + 2)*81;

    const double invM = 1.0 / (double)M_;
    const double sla_d = G0[45 + dd], spr_d = G1[45 + dd];

    float Cr[9], Pr[9], Br[9];
    #pragma unroll
    for (int e = 0; e < 9; e++) {
        const int lo = (dd < e) ? dd : e;
        const int hi = (dd < e) ? e : dd;
        const int tri = lo*9 - (lo*(lo-1))/2 + (hi - lo);
        const double sla_e = G0[45 + e], spr_e = G1[45 + e];
        Cr[e] = (float)(G0[tri] - sla_d*sla_e*invM + ((e == dd) ? ALPHA : 0.0));
        Pr[e] = (float)(G1[tri] - spr_d*spr_e*invM + ((e == dd) ? ALPHA : 0.0));
        Br[e] = (float)(G2[dd*9 + e] - sla_d*spr_e*invM);
    }

    float Lr[9], Dinv[9];
    #pragma unroll
    for (int k = 0; k < 9; k++) {
        const float pkk = __shfl_sync(FULLM, Pr[k], k);
        const float rs  = rsqrtf(fmaxf(pkk, 1e-30f));
        const float ldk = Pr[k] * rs;
        Lr[k]   = ldk;
        Dinv[k] = rs;
        #pragma unroll
        for (int j = 0; j < 9; j++)
            if (j > k) Pr[j] -= ldk * __shfl_sync(FULLM, ldk, j);
    }

    float Wr[9];
    #pragma unroll
    for (int e = 0; e < 9; e++) {
        float s = Br[e];
        #pragma unroll
        for (int k = 0; k < 9; k++)
            if (k < e) s -= Wr[k] * __shfl_sync(FULLM, Lr[k], e);
        Wr[e] = s * Dinv[e];
    }

    #pragma unroll
    for (int e = 0; e < 9; e++) {
        float s = 0.f;
        #pragma unroll
        for (int k = 0; k < 9; k++)
            s += Wr[k] * __shfl_sync(FULLM, Wr[k], e);
        Cr[e] -= s;
    }

    float dprod = 1.f;
    #pragma unroll
    for (int k = 0; k < 9; k++) {
        const float akk = __shfl_sync(FULLM, Cr[k], k);
        const float as  = fmaxf(akk, 1e-30f);
        const float rs  = rsqrtf(as);
        const float lkk = as * rs;
        dprod *= (lkk + 1e-8f);
        const float ldk = Cr[k] * rs;
        #pragma unroll
        for (int j = 0; j < 9; j++)
            if (j > k) Cr[j] -= ldk * __shfl_sync(FULLM, ldk, j);
    }

    // last block through combines, writes output, and self-resets state
    if (d == 0) {
        atomicAdd(&g_rmi, (double)logf(dprod));
        __threadfence();
        const int prev = atomicAdd(&g_done, 1);
        if (prev == NC - 1) {
            const double rmi_total = g_rmi / (double)(N_ * 9);
            const double bce_loss  = g_bce / (g_valid + 1.0);
            outp[0] = (float)(0.5 * bce_loss + 0.5 * rmi_total);
            // reset for next graph replay (all NC blocks already arrived)
            g_bce = 0.0; g_valid = 0.0; g_rmi = 0.0;
            __threadfence();
            g_done = 0;
        }
    }
}

// ------------------------- launch ------------------------------------------
extern "C" void kernel_launch(void* const* d_in, const int* in_sizes, int n_in,
                              void* d_out, int out_size) {
    const float* logits = (const float*)d_in[0];
    const void*  labels = d_in[1];

    dim3 gp(PH, N_, CSPLIT);
    k_pool_bce<<<gp, 192>>>(logits, labels);
    dim3 g2(NC, RSPLIT, 4);
    k_gram_all<<<g2, 192>>>();
    k_finalize<<<NC, 32>>>((float*)d_out);
}

// round 17
// speedup vs baseline: 1.0798x; 1.0033x over previous
#include <cuda_runtime.h>
#include <math.h>
#include <float.h>

#define N_      4
#define C_      21
#define H_      512
#define W_      512
#define HW      (H_*W_)
#define PH      171
#define PP      (PH*PH)      // 29241
#define NH      169
#define M_      (NH*NH)      // 28561
#define NC      (N_*C_)      // 84
#define ALPHA   5e-4
#define CLIPMIN 1e-6f
#define RSPLIT  7
#define ROWCH   ((NH + RSPLIT - 1) / RSPLIT)   // 25
#define GRAMSZ  (NC*3*81)
#define CSPLIT  3
#define CPB     (C_ / CSPLIT)    // 7 classes per block
#define FULLM   0xffffffffu

// ------------------------- device scratch ----------------------------------
// +PH padding: gram kernels prefetch one row beyond the last window row.
__device__ float    g_la[NC*PP + PH];
__device__ float    g_pr[NC*PP + PH];
__device__ unsigned g_labbits[NC*PH*6 + 8];   // per (nc,row): 6 x 32-col bitmask
__device__ double   g_gram[GRAMSZ];
__device__ double   g_bce;      // zero-init at load; self-reset each run
__device__ double   g_valid;
__device__ double   g_rmi;
__device__ int      g_done;

// ------------------------- cp.async helpers --------------------------------
__device__ __forceinline__ void cp_async16(unsigned saddr, const void* gaddr,
                                           int szbytes) {
    asm volatile("cp.async.cg.shared.global [%0], [%1], 16, %2;\n"
                 :: "r"(saddr), "l"(gaddr), "r"(szbytes) : "memory");
}
#define CP_COMMIT() asm volatile("cp.async.commit_group;\n" ::: "memory")
#define CP_WAIT0()  asm volatile("cp.async.wait_group 0;\n" ::: "memory")

// ------------------------- kernel 1: pool + BCE ----------------------------
// Block = (pooled row i, batch n, class-group zc). Handles CPB classes.
// cp.async double-buffered staging; int8 label cache keeps smem/CTA ~14KB
// so 6 CTAs/SM fit (smem was the occupancy binder at int32 labels).
__global__ void __launch_bounds__(192)
k_pool_bce(const float* __restrict__ logits, const void* __restrict__ labv) {
    const int i   = blockIdx.x;        // pooled row 0..170
    const int n   = blockIdx.y;
    const int zc  = blockIdx.z;
    const int c0  = zc * CPB;
    const int tid = threadIdx.x;
    const int y0  = 3*i - 1;

    // zero gram accumulators (zc==0 blocks; complete before gram launch)
    if (zc == 0) {
        const int gt = (n*gridDim.x + i)*192 + tid;
        if (gt < GRAMSZ) g_gram[gt] = 0.0;
    }

    __shared__ int         s_is64;
    __shared__ float4      slog4[2][3][128];
    __shared__ signed char slab[3][512];       // labels fit in int8

    const int ncbase = n * C_;
    const float* __restrict__ lbase = logits + (size_t)ncbase * HW;

    // per-thread staging slots: k0=tid (row r0 in {0,1}), k1=tid+192 (r in {1,2})
    const int r0 = tid >> 7, q0 = tid & 127;
    const int k1 = tid + 192;
    const int r1 = k1 >> 7,  q1 = k1 & 127;
    const int sz0 = (i > 0 || r0 > 0) ? 16 : 0;      // only i==0,r==0 clipped
    const int goff0 = ((y0 + r0 < 0) ? 0 : (y0 + r0))*W_ + 4*q0;
    const int goff1 = (y0 + r1)*W_ + 4*q1;
    const unsigned sbase0 = (unsigned)__cvta_generic_to_shared(&slog4[0][0][0]);
    const unsigned dst0a = sbase0 + tid*16, dst1a = sbase0 + k1*16;
    const unsigned dst0b = dst0a + 3*128*16, dst1b = dst1a + 3*128*16;

    auto stage = [&](int b, int c) {
        const float* __restrict__ src = lbase + (size_t)c * HW;
        cp_async16(b ? dst0b : dst0a, src + goff0, sz0);
        cp_async16(b ? dst1b : dst1a, src + goff1, 16);
        CP_COMMIT();
    };

    // kick off first class copy ASAP (independent of label staging)
    stage(0, c0);

    // parallel dtype sniff: int64 labels (<21) have zero odd int32 words
    if (tid < 32) {
        const int* p = (const int*)labv;
        const int o = p[2*tid + 1] | p[2*(tid + 32) + 1];
        const unsigned bal = __ballot_sync(FULLM, o != 0);
        if (tid == 0) s_is64 = (bal == 0);
    }
    __syncthreads();

    // stage labels for the 3 rows (validated class or -1)
    {
        const bool is64 = (s_is64 != 0);
        const long long* L64 = (const long long*)labv;
        const int*       L32 = (const int*)labv;
        #pragma unroll
        for (int k = tid; k < 3*512; k += 192) {
            const int r = k >> 9, x = k & 511;
            const int y = y0 + r;
            int lv = -1;
            if ((unsigned)y < (unsigned)H_) {
                const int gidx = (n*H_ + y)*W_ + x;
                lv = is64 ? (int)L64[gidx] : L32[gidx];
            }
            slab[r][x] = (signed char)(((unsigned)lv < (unsigned)C_) ? lv : -1);
        }
    }
    __syncthreads();

    // per-cell label metadata (registers, compile-time indexed)
    const int j  = tid;                // cell column
    const int x0 = 3*j - 1;
    int labk[9];
    int xs[3];                         // clamped column offsets
    unsigned vmask = 0, labmask = 0;
    int valid = 0;
    if (j < PH) {
        #pragma unroll
        for (int dx = 0; dx < 3; dx++) {
            const int x = x0 + dx;
            xs[dx] = (x < 0) ? 0 : ((x > 511) ? 511 : x);
        }
        #pragma unroll
        for (int s = 0; s < 9; s++) {
            const int x = x0 + (s % 3);
            const bool inb = ((unsigned)x < (unsigned)W_);
            const int lv = inb ? (int)slab[s/3][x] : -1;
            labk[s] = lv;
            if (lv >= 0) { vmask |= (1u << s); valid++; labmask |= (1u << lv); }
        }
    }

    // label bitmasks (zc==0 only): warp w covers columns w*32..w*32+31
    if (zc == 0) {
        const int lane = tid & 31, wid = tid >> 5;
        #pragma unroll
        for (int c = 0; c < C_; c++) {
            const unsigned bits = __ballot_sync(FULLM, (labmask >> c) & 1u);
            if (lane == 0)
                g_labbits[(size_t)((ncbase + c)*PH + i)*6 + wid] = bits;
        }
    }

    float bce_acc = 0.f;
    const int cell = i*PH + j;
    const bool full = (vmask == 0x1FFu);
    float* __restrict__ pp = g_pr + (size_t)(ncbase + c0)*PP + cell;
    float* __restrict__ pl = g_la + (size_t)(ncbase + c0)*PP + cell;

    #pragma unroll 1
    for (int cc = 0; cc < CPB; cc++) {
        const int c = c0 + cc;
        const int b = cc & 1;
        CP_WAIT0();          // class-c copy complete (issued last iteration)
        __syncthreads();     // all threads: data visible, prev compute done
        if (cc + 1 < CPB) stage(1 - b, c + 1);   // overlaps compute below

        if (j < PH) {
            const float* slog = (const float*)slog4[b];   // [3][512]
            float maxv = -FLT_MAX;
            float prod = 1.f;          // prod over valid pixels of (1+e^{-|x|})
            float racc = 0.f;          // sum relu(lab==c ? -x : x)
            if (full) {
                #pragma unroll
                for (int s = 0; s < 9; s++) {
                    const float xv = slog[xs[s % 3] + (s/3)*512];
                    maxv = fmaxf(maxv, xv);
                    const float t = __expf(-fabsf(xv));
                    prod = fmaf(prod, t, prod);
                    const float xv2 = (labk[s] == c) ? -xv : xv;
                    racc += fmaxf(xv2, 0.f);
                }
            } else {
                #pragma unroll
                for (int s = 0; s < 9; s++) {
                    float xv = slog[xs[s % 3] + (s/3)*512];
                    xv = ((vmask >> s) & 1u) ? xv : -FLT_MAX;
                    maxv = fmaxf(maxv, xv);
                    const float t = __expf(-fabsf(xv));
                    prod = fmaf(prod, t, prod);
                    const float xv2 = (labk[s] == c) ? -xv : xv;
                    racc += fmaxf(xv2, 0.f);
                }
            }
            bce_acc += racc + __logf(prod);
            // sigmoid(maxv); empty cell: maxv=-FLT_MAX -> exp=inf -> sg=0
            const float sg = __fdividef(1.f, 1.f + __expf(-maxv));
            pp[0] = sg + CLIPMIN;
            pl[0] = ((labmask >> c) & 1u) ? 1.f : 0.f;
        }
        pp += PP;
        pl += PP;
    }

    // block reduce -> atomic (valid only from zc==0 to avoid triple count)
    double b = (double)bce_acc, v = (zc == 0) ? (double)valid : 0.0;
    #pragma unroll
    for (int o = 16; o > 0; o >>= 1) {
        b += __shfl_down_sync(FULLM, b, o);
        v += __shfl_down_sync(FULLM, v, o);
    }
    __shared__ double sb[6], sv[6];
    const int lane = tid & 31, wid = tid >> 5;
    if (lane == 0) { sb[wid] = b; sv[wid] = v; }
    __syncthreads();
    if (tid == 0) {
        double tb = 0, tv = 0;
        #pragma unroll
        for (int w = 0; w < 6; w++) { tb += sb[w]; tv += sv[w]; }
        atomicAdd(&g_bce, tb);
        if (zc == 0) atomicAdd(&g_valid, tv);
    }
}

// ------------------------- gram epilogue: block reduce, few atomics --------
template<int NACC>
__device__ __forceinline__ void block_reduce(const float* acc,
                                             float (*sred)[54],
                                             float* outv /*size NACC*/) {
    const int lane = threadIdx.x & 31, wid = threadIdx.x >> 5;
    #pragma unroll
    for (int k = 0; k < NACC; k++) {
        float x = acc[k];
        #pragma unroll
        for (int o = 16; o > 0; o >>= 1) x += __shfl_xor_sync(FULLM, x, o);
        if (lane == 0) sred[wid][k] = x;
    }
    __syncthreads();
    if (threadIdx.x < NACC) {
        float s = 0.f;
        #pragma unroll
        for (int w = 0; w < 6; w++) s += sred[w][threadIdx.x];
        outv[threadIdx.x] = s;
    }
}

// ------------------------- la-self Gram via popcount -----------------------
__device__ __forceinline__ void self_la_bits(const unsigned* __restrict__ Wb,
                                             int i0, int i1,
                                             double* __restrict__ out,
                                             float (*sred)[54]) {
    int acc[54];
    #pragma unroll
    for (int k = 0; k < 54; k++) acc[k] = 0;

    const int t = threadIdx.x;
    const int nrows = i1 - i0;
    if (t < 6*nrows) {
        const int q = t % 6;
        const int i = i0 + t / 6;
        const unsigned vm = (q == 5) ? 0x1FFu : 0xFFFFFFFFu;  // samples j<169
        unsigned bd[9];
        #pragma unroll
        for (int dy = 0; dy < 3; dy++) {
            const unsigned lo = Wb[(size_t)(i+dy)*6 + q];
            const unsigned hi = (q < 5) ? Wb[(size_t)(i+dy)*6 + q + 1] : 0u;
            #pragma unroll
            for (int dx = 0; dx < 3; dx++)
                bd[dy*3+dx] = __funnelshift_r(lo, hi, dx) & vm;
        }
        int k = 0;
        #pragma unroll
        for (int d = 0; d < 9; d++)
            #pragma unroll
            for (int e = d; e < 9; e++)
                acc[k++] += __popc(bd[d] & bd[e]);
        #pragma unroll
        for (int d = 0; d < 9; d++) acc[45 + d] += __popc(bd[d]);
    }

    float facc[54];
    #pragma unroll
    for (int k = 0; k < 54; k++) facc[k] = (float)acc[k];
    __shared__ float outv[54];
    block_reduce<54>(facc, sred, outv);
    if (threadIdx.x < 54) atomicAdd(&out[threadIdx.x], (double)outv[threadIdx.x]);
}

// ------------------------- float gram bodies -------------------------------
__device__ __forceinline__ void self_body(const float* __restrict__ A0,
                                          int i0, int i1,
                                          double* __restrict__ out, int j,
                                          float (*sred)[54]) {
    float acc[54];
    #pragma unroll
    for (int k = 0; k < 54; k++) acc[k] = 0.f;

    if (j < NH) {
        const float* __restrict__ A = A0 + i0*PH + j;
        float w0[3], w1[3], nxt[3];
        #pragma unroll
        for (int c = 0; c < 3; c++) w0[c] = A[c];
        A += PH;
        #pragma unroll
        for (int c = 0; c < 3; c++) w1[c] = A[c];
        A += PH;
        #pragma unroll
        for (int c = 0; c < 3; c++) nxt[c] = A[c];
        A += PH;

        #pragma unroll 2
        for (int i = i0; i < i1; i++) {
            float a[9] = { w0[0], w0[1], w0[2],
                           w1[0], w1[1], w1[2],
                           nxt[0], nxt[1], nxt[2] };
            #pragma unroll
            for (int c = 0; c < 3; c++) nxt[c] = A[c];
            A += PH;

            int k = 0;
            #pragma unroll
            for (int d = 0; d < 9; d++)
                #pragma unroll
                for (int e = d; e < 9; e++)
                    acc[k++] += a[d] * a[e];
            #pragma unroll
            for (int d = 0; d < 9; d++) acc[45 + d] += a[d];

            #pragma unroll
            for (int c = 0; c < 3; c++) { w0[c] = w1[c]; w1[c] = a[6 + c]; }
        }
    }

    __shared__ float outv[54];
    block_reduce<54>(acc, sred, outv);
    if (threadIdx.x < 54) atomicAdd(&out[threadIdx.x], (double)outv[threadIdx.x]);
}

template<int EL, int NE>
__device__ __forceinline__ void cross_body(const float* __restrict__ Ab,
                                           const float* __restrict__ Bb,
                                           int i0, int i1,
                                           double* __restrict__ out, int j,
                                           float (*sred)[54]) {
    float acc[9*NE];
    #pragma unroll
    for (int k = 0; k < 9*NE; k++) acc[k] = 0.f;

    if (j < NH) {
        const float* __restrict__ A = Ab + i0*PH + j;
        const float* __restrict__ B = Bb + i0*PH + j;
        float wa0[3], wa1[3], na[3];
        float wb0[3], wb1[3], nb[3];
        #pragma unroll
        for (int c = 0; c < 3; c++) { wa0[c] = A[c]; wb0[c] = B[c]; }
        A += PH; B += PH;
        #pragma unroll
        for (int c = 0; c < 3; c++) { wa1[c] = A[c]; wb1[c] = B[c]; }
        A += PH; B += PH;
        #pragma unroll
        for (int c = 0; c < 3; c++) { na[c] = A[c]; nb[c] = B[c]; }
        A += PH; B += PH;

        #pragma unroll 2
        for (int i = i0; i < i1; i++) {
            float a[9] = { wa0[0], wa0[1], wa0[2],
                           wa1[0], wa1[1], wa1[2],
                           na[0],  na[1],  na[2] };
            float b[9] = { wb0[0], wb0[1], wb0[2],
                           wb1[0], wb1[1], wb1[2],
                           nb[0],  nb[1],  nb[2] };
            #pragma unroll
            for (int c = 0; c < 3; c++) { na[c] = A[c]; nb[c] = B[c]; }
            A += PH; B += PH;

            #pragma unroll
            for (int d = 0; d < 9; d++)
                #pragma unroll
                for (int e = 0; e < NE; e++)
                    acc[d*NE + e] += a[d] * b[EL + e];

            #pragma unroll
            for (int c = 0; c < 3; c++) {
                wa0[c] = wa1[c]; wa1[c] = a[6 + c];
                wb0[c] = wb1[c]; wb1[c] = b[6 + c];
            }
        }
    }

    __shared__ float outv[54];
    block_reduce<9*NE>(acc, sred, outv);
    if (threadIdx.x < 9*NE) {
        const int d = threadIdx.x / NE, e = EL + (threadIdx.x % NE);
        atomicAdd(&out[d*9 + e], (double)outv[threadIdx.x]);
    }
}

// ------------------------- kernel 2: all Grams, one launch -----------------
__global__ void __launch_bounds__(192)
k_gram_all() {
    __shared__ float sred[6][54];
    const int nc = blockIdx.x;
    const int z  = blockIdx.z;
    const int j  = threadIdx.x;
    const int i0 = blockIdx.y * ROWCH;
    const int i1 = (i0 + ROWCH < NH) ? (i0 + ROWCH) : NH;
    const size_t base = (size_t)nc * PP;
    double* __restrict__ out = g_gram + (size_t)(nc*3) * 81;

    if (z == 0)      self_la_bits(g_labbits + (size_t)nc*PH*6, i0, i1, out, sred);
    else if (z == 1) self_body(g_pr + base, i0, i1, out + 81, j, sred);
    else if (z == 2) cross_body<0,5>(g_la + base, g_pr + base, i0, i1, out + 162, j, sred);
    else             cross_body<5,4>(g_la + base, g_pr + base, i0, i1, out + 162, j, sred);
}

// ------------------------- kernel 3: linear algebra + last-block combine ---
__global__ void __launch_bounds__(32)
k_finalize(float* __restrict__ outp) {
    const int nc = blockIdx.x;
    const int d  = threadIdx.x;
    const int dd = (d < 9) ? d : 0;

    const double* __restrict__ G0 = g_gram + (size_t)(nc*3 + 0)*81;
    const double* __restrict__ G1 = g_gram + (size_t)(nc*3 + 1)*81;
    const double* __restrict__ G2 = g_gram + (size_t)(nc*3 + 2)*81;

    const double invM = 1.0 / (double)M_;
    const double sla_d = G0[45 + dd], spr_d = G1[45 + dd];

    float Cr[9], Pr[9], Br[9];
    #pragma unroll
    for (int e = 0; e < 9; e++) {
        const int lo = (dd < e) ? dd : e;
        const int hi = (dd < e) ? e : dd;
        const int tri = lo*9 - (lo*(lo-1))/2 + (hi - lo);
        const double sla_e = G0[45 + e], spr_e = G1[45 + e];
        Cr[e] = (float)(G0[tri] - sla_d*sla_e*invM + ((e == dd) ? ALPHA : 0.0));
        Pr[e] = (float)(G1[tri] - spr_d*spr_e*invM + ((e == dd) ? ALPHA : 0.0));
        Br[e] = (float)(G2[dd*9 + e] - sla_d*spr_e*invM);
    }

    float Lr[9], Dinv[9];
    #pragma unroll
    for (int k = 0; k < 9; k++) {
        const float pkk = __shfl_sync(FULLM, Pr[k], k);
        const float rs  = rsqrtf(fmaxf(pkk, 1e-30f));
        const float ldk = Pr[k] * rs;
        Lr[k]   = ldk;
        Dinv[k] = rs;
        #pragma unroll
        for (int j = 0; j < 9; j++)
            if (j > k) Pr[j] -= ldk * __shfl_sync(FULLM, ldk, j);
    }

    float Wr[9];
    #pragma unroll
    for (int e = 0; e < 9; e++) {
        float s = Br[e];
        #pragma unroll
        for (int k = 0; k < 9; k++)
            if (k < e) s -= Wr[k] * __shfl_sync(FULLM, Lr[k], e);
        Wr[e] = s * Dinv[e];
    }

    #pragma unroll
    for (int e = 0; e < 9; e++) {
        float s = 0.f;
        #pragma unroll
        for (int k = 0; k < 9; k++)
            s += Wr[k] * __shfl_sync(FULLM, Wr[k], e);
        Cr[e] -= s;
    }

    float dprod = 1.f;
    #pragma unroll
    for (int k = 0; k < 9; k++) {
        const float akk = __shfl_sync(FULLM, Cr[k], k);
        const float as  = fmaxf(akk, 1e-30f);
        const float rs  = rsqrtf(as);
        const float lkk = as * rs;
        dprod *= (lkk + 1e-8f);
        const float ldk = Cr[k] * rs;
        #pragma unroll
        for (int j = 0; j < 9; j++)
            if (j > k) Cr[j] -= ldk * __shfl_sync(FULLM, ldk, j);
    }

    // last block through combines, writes output, and self-resets state
    if (d == 0) {
        atomicAdd(&g_rmi, (double)logf(dprod));
        __threadfence();
        const int prev = atomicAdd(&g_done, 1);
        if (prev == NC - 1) {
            const double rmi_total = g_rmi / (double)(N_ * 9);
            const double bce_loss  = g_bce / (g_valid + 1.0);
            outp[0] = (float)(0.5 * bce_loss + 0.5 * rmi_total);
            // reset for next graph replay (all NC blocks already arrived)
            g_bce = 0.0; g_valid = 0.0; g_rmi = 0.0;
            __threadfence();
            g_done = 0;
        }
    }
}

// ------------------------- launch ------------------------------------------
extern "C" void kernel_launch(void* const* d_in, const int* in_sizes, int n_in,
                              void* d_out, int out_size) {
    const float* logits = (const float*)d_in[0];
    const void*  labels = d_in[1];

    dim3 gp(PH, N_, CSPLIT);
    k_pool_bce<<<gp, 192>>>(logits, labels);
    dim3 g2(NC, RSPLIT, 4);
    k_gram_all<<<g2, 192>>>();
    k_finalize<<<NC, 32>>>((float*)d_out);
}